// round 3
// baseline (speedup 1.0000x reference)
#include <cuda_runtime.h>

// Geometry: [B=2, C=1, D=160, H=192, W=160] fp32.
#define Bsz 2
#define Dd  160
#define Hh  192
#define Ww  160
#define HW  (Hh * Ww)
#define DHW (Dd * HW)
#define NTOT (Bsz * DHW)
#define INV_V (1.0f / 729.0f)
#define EPSL 1e-6f

#define TW 32          // tile width  (W)
#define TH 32          // tile height (H)
#define TWH 40         // halo tile width
#define THH 40         // halo tile height
#define DCB 20         // D outputs per block
#define NPL (DCB + 8)  // planes swept per block (warmup 8)
#define NTHR 1024

// Mean fields Mt, Mp (stage A -> stage B). 78.6 MB static device scratch.
__device__ float g_mean[2][NTOT];

__device__ __forceinline__ int clampi(int v, int lo, int hi) {
    return min(max(v, lo), hi);
}

__global__ void zero_out_k(float* o) { *o = 0.f; }

// ===========================================================================
// Stage A: fully fused 9x9x9 box sum of t and p -> mean fields (x 1/729).
// Block: 1024 threads, tile 32x32 (H,W), sweeps D with a 9-plane smem ring.
// Dynamic smem: sIn 2*1600, sW 2*1280, ring 2*9*1024  = 24192 floats (96768B)
// ===========================================================================
__global__ __launch_bounds__(NTHR, 1)
void stageA(const float* __restrict__ t, const float* __restrict__ p) {
    extern __shared__ float sm[];
    float* sIn0 = sm;                 // t halo plane [40][40]
    float* sIn1 = sm + 1600;          // p halo plane
    float* sW   = sm + 3200;          // W-sums [2][40][32]
    float* ring = sm + 5760;          // [2][9][8][32][4]

    const int tid = threadIdx.x;
    const int twi = blockIdx.x % 5, thi = blockIdx.x / 5;
    const int w0 = twi * TW, h0 = thi * TH;
    const int d0 = blockIdx.y * DCB;
    const long volBase = (long)blockIdx.z * DHW;

    // phase 1 mapping: each thread loads up to 2 halo points (1600 total)
    const int i1 = tid, i2 = tid + NTHR;
    const bool has2 = (i2 < THH * TWH);
    const int off1 = clampi(h0 - 4 + i1 / TWH, 0, Hh - 1) * Ww
                   + clampi(w0 - 4 + i1 % TWH, 0, Ww - 1);
    const int off2 = clampi(h0 - 4 + i2 / TWH, 0, Hh - 1) * Ww
                   + clampi(w0 - 4 + i2 % TWH, 0, Ww - 1);

    // phase 2 mapping: unit = (field, halo row, 4-col strip): 2*40*8 = 640
    const bool act2 = tid < 640;
    const int f2 = tid / 320, r2 = (tid % 320) / 8, cs2 = tid % 8;

    // phase 3 mapping: unit = (field, 4-row h-strip, w col): 2*8*32 = 512
    const bool act3 = tid < 512;
    const int f3 = tid / 256, hs3 = (tid % 256) / 32, tx3 = tid % 32;

    float4 run = make_float4(0.f, 0.f, 0.f, 0.f);
    for (int i = tid; i < 2 * 9 * 1024; i += NTHR) ring[i] = 0.f;

    int q = d0 - 4;
    // prefetch first plane into registers
    float va1, vb1, va2 = 0.f, vb2 = 0.f;
    {
        const long pb = volBase + (long)clampi(q, 0, Dd - 1) * HW;
        va1 = __ldg(t + pb + off1); vb1 = __ldg(p + pb + off1);
        if (has2) { va2 = __ldg(t + pb + off2); vb2 = __ldg(p + pb + off2); }
    }

    int slot = 0;
    for (int iter = 0; iter < NPL; ++iter, ++q) {
        // P1: stage plane into smem
        sIn0[i1] = va1; sIn1[i1] = vb1;
        if (has2) { sIn0[i2] = va2; sIn1[i2] = vb2; }
        __syncthreads();
        // prefetch next plane (overlaps P2/P3)
        if (iter + 1 < NPL) {
            const long pb = volBase + (long)clampi(q + 1, 0, Dd - 1) * HW;
            va1 = __ldg(t + pb + off1); vb1 = __ldg(p + pb + off1);
            if (has2) { va2 = __ldg(t + pb + off2); vb2 = __ldg(p + pb + off2); }
        }
        // P2: 9-tap W-sums, 4 outputs per unit via running sum
        if (act2) {
            const float4* row = (const float4*)((f2 ? sIn1 : sIn0) + r2 * TWH);
            float4 x0 = row[cs2], x1 = row[cs2 + 1], x2 = row[cs2 + 2];
            float s0 = x0.x + x0.y + x0.z + x0.w + x1.x + x1.y + x1.z + x1.w + x2.x;
            float s1 = s0 - x0.x + x2.y;
            float s2 = s1 - x0.y + x2.z;
            float s3 = s2 - x0.z + x2.w;
            ((float4*)(sW + f2 * 1280 + r2 * TW))[cs2] = make_float4(s0, s1, s2, s3);
        }
        __syncthreads();
        // P3: 9-tap H-sums (running, 4 per unit) + 9-plane D ring update
        if (act3) {
            const float* col = sW + f3 * 1280 + hs3 * 4 * TW + tx3;
            float v0 = col[0],      v1 = col[32],     v2 = col[64],
                  v3 = col[96],     v4 = col[128],    v5 = col[160],
                  v6 = col[192],    v7 = col[224],    v8 = col[256],
                  v9 = col[288],    v10 = col[320],   v11 = col[352];
            float h0s = v0 + v1 + v2 + v3 + v4 + v5 + v6 + v7 + v8;
            float h1s = h0s - v0 + v9;
            float h2s = h1s - v1 + v10;
            float h3s = h2s - v2 + v11;
            float4* rg = (float4*)(ring + ((f3 * 9 + slot) * 256 + hs3 * 32 + tx3) * 4);
            float4 old = *rg;
            run.x += h0s - old.x; run.y += h1s - old.y;
            run.z += h2s - old.z; run.w += h3s - old.w;
            *rg = make_float4(h0s, h1s, h2s, h3s);
            const int d = q - 4;
            if (d >= d0) {
                float* o = (f3 ? g_mean[1] : g_mean[0]) + volBase + (long)d * HW
                         + (h0 + hs3 * 4) * Ww + (w0 + tx3);
                o[0]      = run.x * INV_V;
                o[Ww]     = run.y * INV_V;
                o[2 * Ww] = run.z * INV_V;
                o[3 * Ww] = run.w * INV_V;
            }
        }
        slot = (slot == 8) ? 0 : slot + 1;
    }
}

// ===========================================================================
// Stage B: centered products (tc*pc, tc^2, pc^2) box-summed 9x9x9, fused with
// cc = clip((A^2+eps)/(B*C+eps)) and the global mean reduction.
// Dynamic smem: sCt/sCp 2*1600, sW 3*1280, ring 3*9*1024, sComb 3*1024
//             = 37760 floats (151040 B)
// ===========================================================================
__global__ __launch_bounds__(NTHR, 1)
void stageB(const float* __restrict__ t, const float* __restrict__ p,
            float* __restrict__ out) {
    extern __shared__ float sm[];
    float* sCt  = sm;                 // tc halo plane [40][40]
    float* sCp  = sm + 1600;          // pc halo plane
    float* sW   = sm + 3200;          // W-sums [3][40][32]
    float* ring = sm + 7040;          // [3][9][8][32][4]
    float* sCb  = sm + 34688;         // combine buffer [3][8][32][4]

    const int tid = threadIdx.x;
    const int twi = blockIdx.x % 5, thi = blockIdx.x / 5;
    const int w0 = twi * TW, h0 = thi * TH;
    const int d0 = blockIdx.y * DCB;
    const long volBase = (long)blockIdx.z * DHW;

    const int i1 = tid, i2 = tid + NTHR;
    const bool has2 = (i2 < THH * TWH);
    const int off1 = clampi(h0 - 4 + i1 / TWH, 0, Hh - 1) * Ww
                   + clampi(w0 - 4 + i1 % TWH, 0, Ww - 1);
    const int off2 = clampi(h0 - 4 + i2 / TWH, 0, Hh - 1) * Ww
                   + clampi(w0 - 4 + i2 % TWH, 0, Ww - 1);

    const bool act2 = tid < 960;                    // 3 fields * 40 rows * 8 strips
    const int f2 = tid / 320, r2 = (tid % 320) / 8, cs2 = tid % 8;

    const bool act3 = tid < 768;                    // 3 fields * 8 strips * 32 cols
    const int f3 = tid / 256, hs3 = (tid % 256) / 32, tx3 = tid % 32;

    float4 run = make_float4(0.f, 0.f, 0.f, 0.f);
    float acc = 0.f;
    for (int i = tid; i < 3 * 9 * 1024; i += NTHR) ring[i] = 0.f;

    const float* mt = g_mean[0];
    const float* mp = g_mean[1];

    int q = d0 - 4;
    float tc1, pc1, tc2 = 0.f, pc2 = 0.f;
    {
        const long pb = volBase + (long)clampi(q, 0, Dd - 1) * HW;
        tc1 = __ldg(t + pb + off1) - __ldg(mt + pb + off1);
        pc1 = __ldg(p + pb + off1) - __ldg(mp + pb + off1);
        if (has2) {
            tc2 = __ldg(t + pb + off2) - __ldg(mt + pb + off2);
            pc2 = __ldg(p + pb + off2) - __ldg(mp + pb + off2);
        }
    }

    int slot = 0;
    for (int iter = 0; iter < NPL; ++iter, ++q) {
        sCt[i1] = tc1; sCp[i1] = pc1;
        if (has2) { sCt[i2] = tc2; sCp[i2] = pc2; }
        __syncthreads();
        if (iter + 1 < NPL) {
            const long pb = volBase + (long)clampi(q + 1, 0, Dd - 1) * HW;
            tc1 = __ldg(t + pb + off1) - __ldg(mt + pb + off1);
            pc1 = __ldg(p + pb + off1) - __ldg(mp + pb + off1);
            if (has2) {
                tc2 = __ldg(t + pb + off2) - __ldg(mt + pb + off2);
                pc2 = __ldg(p + pb + off2) - __ldg(mp + pb + off2);
            }
        }
        // P2: product formation + 9-tap W-sums (4 outputs / unit)
        if (act2) {
            float v0, v1, v2, v3, v4, v5, v6, v7, v8, v9, v10, v11;
            if (f2 == 0) {
                const float4* ra = (const float4*)(sCt + r2 * TWH);
                const float4* rb = (const float4*)(sCp + r2 * TWH);
                float4 a0 = ra[cs2], a1 = ra[cs2 + 1], a2 = ra[cs2 + 2];
                float4 b0 = rb[cs2], b1 = rb[cs2 + 1], b2 = rb[cs2 + 2];
                v0 = a0.x * b0.x; v1 = a0.y * b0.y; v2 = a0.z * b0.z; v3 = a0.w * b0.w;
                v4 = a1.x * b1.x; v5 = a1.y * b1.y; v6 = a1.z * b1.z; v7 = a1.w * b1.w;
                v8 = a2.x * b2.x; v9 = a2.y * b2.y; v10 = a2.z * b2.z; v11 = a2.w * b2.w;
            } else {
                const float4* ra = (const float4*)((f2 == 1 ? sCt : sCp) + r2 * TWH);
                float4 a0 = ra[cs2], a1 = ra[cs2 + 1], a2 = ra[cs2 + 2];
                v0 = a0.x * a0.x; v1 = a0.y * a0.y; v2 = a0.z * a0.z; v3 = a0.w * a0.w;
                v4 = a1.x * a1.x; v5 = a1.y * a1.y; v6 = a1.z * a1.z; v7 = a1.w * a1.w;
                v8 = a2.x * a2.x; v9 = a2.y * a2.y; v10 = a2.z * a2.z; v11 = a2.w * a2.w;
            }
            float s0 = v0 + v1 + v2 + v3 + v4 + v5 + v6 + v7 + v8;
            float s1 = s0 - v0 + v9;
            float s2 = s1 - v1 + v10;
            float s3 = s2 - v2 + v11;
            ((float4*)(sW + f2 * 1280 + r2 * TW))[cs2] = make_float4(s0, s1, s2, s3);
        }
        __syncthreads();
        // P3: H-sums + D ring
        if (act3) {
            const float* col = sW + f3 * 1280 + hs3 * 4 * TW + tx3;
            float v0 = col[0],      v1 = col[32],     v2 = col[64],
                  v3 = col[96],     v4 = col[128],    v5 = col[160],
                  v6 = col[192],    v7 = col[224],    v8 = col[256],
                  v9 = col[288],    v10 = col[320],   v11 = col[352];
            float h0s = v0 + v1 + v2 + v3 + v4 + v5 + v6 + v7 + v8;
            float h1s = h0s - v0 + v9;
            float h2s = h1s - v1 + v10;
            float h3s = h2s - v2 + v11;
            float4* rg = (float4*)(ring + ((f3 * 9 + slot) * 256 + hs3 * 32 + tx3) * 4);
            float4 old = *rg;
            run.x += h0s - old.x; run.y += h1s - old.y;
            run.z += h2s - old.z; run.w += h3s - old.w;
            *rg = make_float4(h0s, h1s, h2s, h3s);
        }
        const int d = q - 4;
        if (d >= d0) {   // uniform across block
            if (act3 && f3 > 0)
                *(float4*)(sCb + f3 * 1024 + (hs3 * 32 + tx3) * 4) = run;
            __syncthreads();
            if (act3 && f3 == 0) {
                float4 vb = *(const float4*)(sCb + 1024 + (hs3 * 32 + tx3) * 4);
                float4 vc = *(const float4*)(sCb + 2048 + (hs3 * 32 + tx3) * 4);
                acc += fminf(fmaxf((run.x * run.x + EPSL) / (vb.x * vc.x + EPSL), 0.f), 1.f);
                acc += fminf(fmaxf((run.y * run.y + EPSL) / (vb.y * vc.y + EPSL), 0.f), 1.f);
                acc += fminf(fmaxf((run.z * run.z + EPSL) / (vb.z * vc.z + EPSL), 0.f), 1.f);
                acc += fminf(fmaxf((run.w * run.w + EPSL) / (vb.w * vc.w + EPSL), 0.f), 1.f);
            }
        }
        slot = (slot == 8) ? 0 : slot + 1;
    }

    // block reduction of acc (only f3==0 units contributed; others hold 0)
    __syncthreads();
    sCt[tid] = acc;
    __syncthreads();
#pragma unroll
    for (int s = 512; s > 0; s >>= 1) {
        if (tid < s) sCt[tid] += sCt[tid + s];
        __syncthreads();
    }
    if (tid == 0) atomicAdd(out, -sCt[0] * (1.0f / (float)NTOT));
}

// ===========================================================================
extern "C" void kernel_launch(void* const* d_in, const int* in_sizes, int n_in,
                              void* d_out, int out_size) {
    const float* t = (const float*)d_in[0];  // y_true
    const float* p = (const float*)d_in[1];  // y_pred
    float* out = (float*)d_out;

    static const int SMEM_A = 24192 * 4;   // 96768 B
    static const int SMEM_B = 37760 * 4;   // 151040 B
    cudaFuncSetAttribute(stageA, cudaFuncAttributeMaxDynamicSharedMemorySize, SMEM_A);
    cudaFuncSetAttribute(stageB, cudaFuncAttributeMaxDynamicSharedMemorySize, SMEM_B);

    dim3 grid(30, Dd / DCB, Bsz);          // (5*6 tiles, 8 D-chunks, 2 batch)
    stageA<<<grid, NTHR, SMEM_A>>>(t, p);
    zero_out_k<<<1, 1>>>(out);
    stageB<<<grid, NTHR, SMEM_B>>>(t, p, out);
}

// round 4
// speedup vs baseline: 1.5965x; 1.5965x over previous
#include <cuda_runtime.h>

// Geometry: [B=2, C=1, D=160, H=192, W=160] fp32.
#define Bsz 2
#define Dd  160
#define Hh  192
#define Ww  160
#define HW  (Hh * Ww)
#define DHW (Dd * HW)
#define NTOT (Bsz * DHW)
#define INV_V (1.0f / 729.0f)
#define EPSL 1e-6f

// WH-kernel tiling: full W rows, CHO output H-rows (+8 halo), padded row stride.
#define CHO 48
#define CHH 56          // CHO + 8
#define RSTR 168        // 4 (left pad) + 160 + 4 (right pad)
#define NT1 640         // blockDim (160, 4)

// D-kernel chunking.
#define CD2 80

// Scratch fields: [0]=St/SA, [1]=Sp/SB, [2]=Mt, [3]=Mp, [4]=SC.  196.6 MB.
__device__ float g_s[5][NTOT];

__device__ __forceinline__ int clampi(int v, int lo, int hi) {
    return min(max(v, lo), hi);
}

__global__ void zero_out_k(float* o) { *o = 0.f; }

// ===========================================================================
// K1: per-plane W+H 9x9 box sums of t and p -> g_s[0], g_s[1].
// Block = one (b, d, H-chunk). Phases: load padded rows -> W strip sums ->
// H running sums + store. Fields processed sequentially to halve smem.
// smem: sIn[56][168] + sW[56][160] = 73472 B.
// ===========================================================================
__global__ __launch_bounds__(NT1, 2)
void k_wh2(const float* __restrict__ t, const float* __restrict__ p) {
    extern __shared__ float sm[];
    float* sIn = sm;                 // padded input rows
    float* sW  = sm + CHH * RSTR;    // W-sums

    const int tx = threadIdx.x, ty = threadIdx.y;
    const int tid = ty * 160 + tx;
    const int h0c = blockIdx.x * CHO;
    const long pl = (long)blockIdx.z * DHW + (long)blockIdx.y * HW;

    for (int f = 0; f < 2; ++f) {
        const float* __restrict__ src = f ? p : t;
        float* __restrict__ dst = g_s[f];
        // ---- load (interior float4 + replicated edge pads) ----
        for (int u = tid; u < CHH * 40; u += NT1) {
            int row = u / 40, c4 = u % 40;
            int gh = clampi(h0c - 4 + row, 0, Hh - 1);
            float4 v = *(const float4*)(src + pl + (long)gh * Ww + c4 * 4);
            *(float4*)(sIn + row * RSTR + 4 + c4 * 4) = v;
        }
        if (tid < CHH * 2) {
            int row = tid >> 1, side = tid & 1;
            int gh = clampi(h0c - 4 + row, 0, Hh - 1);
            float v = src[pl + (long)gh * Ww + (side ? Ww - 1 : 0)];
            float* e = sIn + row * RSTR + (side ? 164 : 0);
            e[0] = v; e[1] = v; e[2] = v; e[3] = v;
        }
        __syncthreads();
        // ---- W: 9-tap running strip sums (4 outputs / unit) ----
        for (int u = tid; u < CHH * 40; u += NT1) {
            int row = u / 40, s = u % 40;
            const float* rp = sIn + row * RSTR + 4 * s;
            float4 x0 = *(const float4*)rp;
            float4 x1 = *(const float4*)(rp + 4);
            float4 x2 = *(const float4*)(rp + 8);
            float s0 = x0.x + x0.y + x0.z + x0.w + x1.x + x1.y + x1.z + x1.w + x2.x;
            float s1 = s0 - x0.x + x2.y;
            float s2 = s1 - x0.y + x2.z;
            float s3 = s2 - x0.z + x2.w;
            *(float4*)(sW + row * 160 + 4 * s) = make_float4(s0, s1, s2, s3);
        }
        __syncthreads();
        // ---- H: running sums over 12-row groups, store ----
        {
            const int r0 = ty * 12;
            const float* c = sW + tx;
            float s = c[(r0 + 0) * 160] + c[(r0 + 1) * 160] + c[(r0 + 2) * 160]
                    + c[(r0 + 3) * 160] + c[(r0 + 4) * 160] + c[(r0 + 5) * 160]
                    + c[(r0 + 6) * 160] + c[(r0 + 7) * 160] + c[(r0 + 8) * 160];
            float* o = dst + pl + (long)(h0c + r0) * Ww + tx;
            o[0] = s;
#pragma unroll
            for (int k = 1; k < 12; ++k) {
                s += c[(r0 + k + 8) * 160] - c[(r0 + k - 1) * 160];
                o[(long)k * Ww] = s;
            }
        }
        __syncthreads();
    }
}

// ===========================================================================
// K2: D-axis 9-tap running box sum of g_s[f] -> g_s[2+f], scaled by 1/729.
// Thread = one (b, hw) column, sweeps CD2 planes. grid (240, D/CD2, B*2).
// ===========================================================================
__global__ __launch_bounds__(128, 8)
void k_d2() {
    const int f = blockIdx.z & 1, b = blockIdx.z >> 1;
    const int hw = blockIdx.x * 128 + threadIdx.x;
    const int d0 = blockIdx.y * CD2;
    const float* __restrict__ S = g_s[f];
    float* __restrict__ M = g_s[2 + f];
    const long base = (long)b * DHW + hw;

    float s = 0.f;
#pragma unroll
    for (int j = -4; j <= 4; ++j)
        s += S[base + (long)clampi(d0 + j, 0, Dd - 1) * HW];
    M[base + (long)d0 * HW] = s * INV_V;
#pragma unroll 4
    for (int d = d0 + 1; d < d0 + CD2; ++d) {
        s += S[base + (long)min(d + 4, Dd - 1) * HW]
           - S[base + (long)max(d - 5, 0) * HW];
        M[base + (long)d * HW] = s * INV_V;
    }
}

// ===========================================================================
// K3: per-plane centered products + W+H box sums.
// Loads tc = t - Mt, pc = p - Mp into padded smem; three passes produce
// WH-box of (tc*pc) -> g_s[0], (tc*tc) -> g_s[1], (pc*pc) -> g_s[4].
// smem: sCt[56][168] + sCp[56][168] + sW[56][160] = 111104 B.
// ===========================================================================
__global__ __launch_bounds__(NT1, 2)
void k_prodwh(const float* __restrict__ t, const float* __restrict__ p) {
    extern __shared__ float sm[];
    float* sCt = sm;
    float* sCp = sm + CHH * RSTR;
    float* sW  = sm + 2 * CHH * RSTR;

    const int tx = threadIdx.x, ty = threadIdx.y;
    const int tid = ty * 160 + tx;
    const int h0c = blockIdx.x * CHO;
    const long pl = (long)blockIdx.z * DHW + (long)blockIdx.y * HW;
    const float* __restrict__ mt = g_s[2];
    const float* __restrict__ mp = g_s[3];

    // ---- load centered fields ----
    for (int u = tid; u < CHH * 40; u += NT1) {
        int row = u / 40, c4 = u % 40;
        int gh = clampi(h0c - 4 + row, 0, Hh - 1);
        const long a = pl + (long)gh * Ww + c4 * 4;
        float4 vt = *(const float4*)(t + a);
        float4 vm = *(const float4*)(mt + a);
        float4 vp = *(const float4*)(p + a);
        float4 vq = *(const float4*)(mp + a);
        *(float4*)(sCt + row * RSTR + 4 + c4 * 4) =
            make_float4(vt.x - vm.x, vt.y - vm.y, vt.z - vm.z, vt.w - vm.w);
        *(float4*)(sCp + row * RSTR + 4 + c4 * 4) =
            make_float4(vp.x - vq.x, vp.y - vq.y, vp.z - vq.z, vp.w - vq.w);
    }
    if (tid < CHH * 2) {
        int row = tid >> 1, side = tid & 1;
        int gh = clampi(h0c - 4 + row, 0, Hh - 1);
        const long a = pl + (long)gh * Ww + (side ? Ww - 1 : 0);
        float vt = t[a] - mt[a];
        float vp = p[a] - mp[a];
        float* e0 = sCt + row * RSTR + (side ? 164 : 0);
        float* e1 = sCp + row * RSTR + (side ? 164 : 0);
        e0[0] = vt; e0[1] = vt; e0[2] = vt; e0[3] = vt;
        e1[0] = vp; e1[1] = vp; e1[2] = vp; e1[3] = vp;
    }
    __syncthreads();

#pragma unroll
    for (int q = 0; q < 3; ++q) {
        float* __restrict__ dst = g_s[q == 0 ? 0 : (q == 1 ? 1 : 4)];
        // ---- W: products + running strip sums ----
        for (int u = tid; u < CHH * 40; u += NT1) {
            int row = u / 40, s = u % 40;
            const float* ra = (q == 2 ? sCp : sCt) + row * RSTR + 4 * s;
            const float* rb = (q == 0 ? sCp : (q == 1 ? sCt : sCp)) + row * RSTR + 4 * s;
            float4 a0 = *(const float4*)ra, a1 = *(const float4*)(ra + 4), a2 = *(const float4*)(ra + 8);
            float4 b0 = *(const float4*)rb, b1 = *(const float4*)(rb + 4), b2 = *(const float4*)(rb + 8);
            float v0 = a0.x * b0.x, v1 = a0.y * b0.y, v2 = a0.z * b0.z, v3 = a0.w * b0.w;
            float v4 = a1.x * b1.x, v5 = a1.y * b1.y, v6 = a1.z * b1.z, v7 = a1.w * b1.w;
            float v8 = a2.x * b2.x, v9 = a2.y * b2.y, v10 = a2.z * b2.z, v11 = a2.w * b2.w;
            float s0 = v0 + v1 + v2 + v3 + v4 + v5 + v6 + v7 + v8;
            float s1 = s0 - v0 + v9;
            float s2 = s1 - v1 + v10;
            float s3 = s2 - v2 + v11;
            *(float4*)(sW + row * 160 + 4 * s) = make_float4(s0, s1, s2, s3);
        }
        __syncthreads();
        // ---- H: running sums + store ----
        {
            const int r0 = ty * 12;
            const float* c = sW + tx;
            float s = c[(r0 + 0) * 160] + c[(r0 + 1) * 160] + c[(r0 + 2) * 160]
                    + c[(r0 + 3) * 160] + c[(r0 + 4) * 160] + c[(r0 + 5) * 160]
                    + c[(r0 + 6) * 160] + c[(r0 + 7) * 160] + c[(r0 + 8) * 160];
            float* o = dst + pl + (long)(h0c + r0) * Ww + tx;
            o[0] = s;
#pragma unroll
            for (int k = 1; k < 12; ++k) {
                s += c[(r0 + k + 8) * 160] - c[(r0 + k - 1) * 160];
                o[(long)k * Ww] = s;
            }
        }
        __syncthreads();
    }
}

// ===========================================================================
// K4: D-axis running box sums of SA,SB,SC + cc + mean reduction.
// ===========================================================================
__global__ __launch_bounds__(128, 8)
void k_d3cc(float* __restrict__ out) {
    const int b = blockIdx.z;
    const int hw = blockIdx.x * 128 + threadIdx.x;
    const int d0 = blockIdx.y * CD2;
    const float* __restrict__ A = g_s[0];
    const float* __restrict__ B = g_s[1];
    const float* __restrict__ C = g_s[4];
    const long base = (long)b * DHW + hw;

    float sa = 0.f, sb = 0.f, sc = 0.f;
#pragma unroll
    for (int j = -4; j <= 4; ++j) {
        long a = base + (long)clampi(d0 + j, 0, Dd - 1) * HW;
        sa += A[a]; sb += B[a]; sc += C[a];
    }
    float acc = fminf(fmaxf(__fdividef(sa * sa + EPSL, sb * sc + EPSL), 0.f), 1.f);
#pragma unroll 4
    for (int d = d0 + 1; d < d0 + CD2; ++d) {
        long ap = base + (long)min(d + 4, Dd - 1) * HW;
        long am = base + (long)max(d - 5, 0) * HW;
        sa += A[ap] - A[am];
        sb += B[ap] - B[am];
        sc += C[ap] - C[am];
        acc += fminf(fmaxf(__fdividef(sa * sa + EPSL, sb * sc + EPSL), 0.f), 1.f);
    }

    __shared__ float red[128];
    red[threadIdx.x] = acc;
    __syncthreads();
#pragma unroll
    for (int s = 64; s > 0; s >>= 1) {
        if (threadIdx.x < s) red[threadIdx.x] += red[threadIdx.x + s];
        __syncthreads();
    }
    if (threadIdx.x == 0) atomicAdd(out, -red[0] * (1.0f / (float)NTOT));
}

// ===========================================================================
extern "C" void kernel_launch(void* const* d_in, const int* in_sizes, int n_in,
                              void* d_out, int out_size) {
    const float* t = (const float*)d_in[0];  // y_true
    const float* p = (const float*)d_in[1];  // y_pred
    float* out = (float*)d_out;

    static const int SM1 = (CHH * RSTR + CHH * 160) * 4;       // 73472 B
    static const int SM3 = (2 * CHH * RSTR + CHH * 160) * 4;   // 111104 B
    cudaFuncSetAttribute(k_wh2,    cudaFuncAttributeMaxDynamicSharedMemorySize, SM1);
    cudaFuncSetAttribute(k_prodwh, cudaFuncAttributeMaxDynamicSharedMemorySize, SM3);

    const dim3 bwh(160, 4);
    const dim3 gwh(Hh / CHO, Dd, Bsz);            // (4, 160, 2)
    const dim3 gd(Bsz * HW / (128 * CD2) * 40, Dd / CD2, 0);  // placeholder, set below

    k_wh2<<<gwh, bwh, SM1>>>(t, p);
    k_d2<<<dim3(Bsz * HW / 256, Dd / CD2, 4), 128>>>();       // (240, 2, 4)
    k_prodwh<<<gwh, bwh, SM3>>>(t, p);
    zero_out_k<<<1, 1>>>(out);
    k_d3cc<<<dim3(Bsz * HW / 256, Dd / CD2, Bsz), 128>>>(out); // (240, 2, 2)
}

// round 5
// speedup vs baseline: 1.8730x; 1.1732x over previous
#include <cuda_runtime.h>
#include <cuda_fp16.h>

// Geometry: [B=2, C=1, D=160, H=192, W=160] fp32.
#define Bsz 2
#define Dd  160
#define Hh  192
#define Ww  160
#define HW  (Hh * Ww)
#define DHW (Dd * HW)
#define NTOT (Bsz * DHW)
#define INV_V (1.0f / 729.0f)
#define EPSL 1e-6f

// WH-kernel tiling: full W rows, CHO output H-rows (+8 halo), padded stride.
#define CHO 48
#define CHH 56          // CHO + 8
#define RSTR 168        // 4 + 160 + 4
#define NT1 640         // blockDim (160, 4)

#define CD2 80          // D-chunk for streaming kernels

// Half-precision intermediate fields: [0]=St/SA [1]=Sp/SB [2]=tc [3]=pc [4]=SC
// 5 * 9.83M * 2B = 98.3 MB static scratch.
__device__ __half g_h[5][NTOT];

__device__ __forceinline__ int clampi(int v, int lo, int hi) {
    return min(max(v, lo), hi);
}

// ===========================================================================
// K1: per-plane W+H 9x9 box sums of t and p -> g_h[0], g_h[1] (fp16).
// Also zeroes the output scalar (first kernel in the stream).
// smem: sIn[56][168] + sW[56][160] fp32 = 73472 B.
// ===========================================================================
__global__ __launch_bounds__(NT1, 2)
void k_wh2(const float* __restrict__ t, const float* __restrict__ p,
           float* __restrict__ out) {
    extern __shared__ float sm[];
    float* sIn = sm;
    float* sW  = sm + CHH * RSTR;

    const int tx = threadIdx.x, ty = threadIdx.y;
    const int tid = ty * 160 + tx;
    if (blockIdx.x == 0 && blockIdx.y == 0 && blockIdx.z == 0 && tid == 0)
        *out = 0.f;
    const int h0c = blockIdx.x * CHO;
    const long pl = (long)blockIdx.z * DHW + (long)blockIdx.y * HW;

    for (int f = 0; f < 2; ++f) {
        const float* __restrict__ src = f ? p : t;
        __half* __restrict__ dst = g_h[f];
        // ---- load padded rows ----
        for (int u = tid; u < CHH * 40; u += NT1) {
            int row = u / 40, c4 = u % 40;
            int gh = clampi(h0c - 4 + row, 0, Hh - 1);
            float4 v = *(const float4*)(src + pl + (long)gh * Ww + c4 * 4);
            *(float4*)(sIn + row * RSTR + 4 + c4 * 4) = v;
        }
        if (tid < CHH * 2) {
            int row = tid >> 1, side = tid & 1;
            int gh = clampi(h0c - 4 + row, 0, Hh - 1);
            float v = src[pl + (long)gh * Ww + (side ? Ww - 1 : 0)];
            float* e = sIn + row * RSTR + (side ? 164 : 0);
            e[0] = v; e[1] = v; e[2] = v; e[3] = v;
        }
        __syncthreads();
        // ---- W: 9-tap running strip sums ----
        for (int u = tid; u < CHH * 40; u += NT1) {
            int row = u / 40, s = u % 40;
            const float* rp = sIn + row * RSTR + 4 * s;
            float4 x0 = *(const float4*)rp;
            float4 x1 = *(const float4*)(rp + 4);
            float4 x2 = *(const float4*)(rp + 8);
            float s0 = x0.x + x0.y + x0.z + x0.w + x1.x + x1.y + x1.z + x1.w + x2.x;
            float s1 = s0 - x0.x + x2.y;
            float s2 = s1 - x0.y + x2.z;
            float s3 = s2 - x0.z + x2.w;
            *(float4*)(sW + row * 160 + 4 * s) = make_float4(s0, s1, s2, s3);
        }
        __syncthreads();
        // ---- H: running sums over 12-row groups, store fp16 ----
        {
            const int r0 = ty * 12;
            const float* c = sW + tx;
            float s = c[(r0 + 0) * 160] + c[(r0 + 1) * 160] + c[(r0 + 2) * 160]
                    + c[(r0 + 3) * 160] + c[(r0 + 4) * 160] + c[(r0 + 5) * 160]
                    + c[(r0 + 6) * 160] + c[(r0 + 7) * 160] + c[(r0 + 8) * 160];
            __half* o = dst + pl + (long)(h0c + r0) * Ww + tx;
            o[0] = __float2half_rn(s);
#pragma unroll
            for (int k = 1; k < 12; ++k) {
                s += c[(r0 + k + 8) * 160] - c[(r0 + k - 1) * 160];
                o[(long)k * Ww] = __float2half_rn(s);
            }
        }
        __syncthreads();
    }
}

// ===========================================================================
// K2: D-axis running box sum of St,Sp -> means; fused centering:
// writes tc = t - Mt, pc = p - Mp as fp16 -> g_h[2], g_h[3].
// Thread = one (b, hw) column. grid (HW/256, D/CD2, B).
// ===========================================================================
__global__ __launch_bounds__(256, 6)
void k_dcenter(const float* __restrict__ t, const float* __restrict__ p) {
    const int b = blockIdx.z;
    const int hw = blockIdx.x * 256 + threadIdx.x;
    const int d0 = blockIdx.y * CD2;
    const __half* __restrict__ St = g_h[0];
    const __half* __restrict__ Sp = g_h[1];
    __half* __restrict__ Tc = g_h[2];
    __half* __restrict__ Pc = g_h[3];
    const long base = (long)b * DHW + hw;

    float sa = 0.f, sb = 0.f;
#pragma unroll
    for (int j = -4; j <= 4; ++j) {
        long a = base + (long)clampi(d0 + j, 0, Dd - 1) * HW;
        sa += __half2float(St[a]);
        sb += __half2float(Sp[a]);
    }
    {
        long a = base + (long)d0 * HW;
        Tc[a] = __float2half_rn(t[a] - sa * INV_V);
        Pc[a] = __float2half_rn(p[a] - sb * INV_V);
    }
#pragma unroll 4
    for (int d = d0 + 1; d < d0 + CD2; ++d) {
        long ap = base + (long)min(d + 4, Dd - 1) * HW;
        long am = base + (long)max(d - 5, 0) * HW;
        sa += __half2float(St[ap]) - __half2float(St[am]);
        sb += __half2float(Sp[ap]) - __half2float(Sp[am]);
        long a = base + (long)d * HW;
        Tc[a] = __float2half_rn(t[a] - sa * INV_V);
        Pc[a] = __float2half_rn(p[a] - sb * INV_V);
    }
}

// ===========================================================================
// K3: per-plane W+H box sums of (tc*pc, tc^2, pc^2) from fp16 tc,pc
// -> g_h[0], g_h[1], g_h[4] (fp16).
// smem: sCt[56][168] + sCp[56][168] + sW[56][160] fp32 = 111104 B.
// ===========================================================================
__global__ __launch_bounds__(NT1, 2)
void k_prodwh() {
    extern __shared__ float sm[];
    float* sCt = sm;
    float* sCp = sm + CHH * RSTR;
    float* sW  = sm + 2 * CHH * RSTR;

    const int tx = threadIdx.x, ty = threadIdx.y;
    const int tid = ty * 160 + tx;
    const int h0c = blockIdx.x * CHO;
    const long pl = (long)blockIdx.z * DHW + (long)blockIdx.y * HW;
    const __half* __restrict__ Tc = g_h[2];
    const __half* __restrict__ Pc = g_h[3];

    // ---- load centered fields (fp16 -> fp32 smem) ----
    for (int u = tid; u < CHH * 40; u += NT1) {
        int row = u / 40, c4 = u % 40;
        int gh = clampi(h0c - 4 + row, 0, Hh - 1);
        const long a = pl + (long)gh * Ww + c4 * 4;
        const __half2* ht = (const __half2*)(Tc + a);
        const __half2* hp = (const __half2*)(Pc + a);
        float2 t0 = __half22float2(ht[0]), t1 = __half22float2(ht[1]);
        float2 p0 = __half22float2(hp[0]), p1 = __half22float2(hp[1]);
        *(float4*)(sCt + row * RSTR + 4 + c4 * 4) = make_float4(t0.x, t0.y, t1.x, t1.y);
        *(float4*)(sCp + row * RSTR + 4 + c4 * 4) = make_float4(p0.x, p0.y, p1.x, p1.y);
    }
    if (tid < CHH * 2) {
        int row = tid >> 1, side = tid & 1;
        int gh = clampi(h0c - 4 + row, 0, Hh - 1);
        const long a = pl + (long)gh * Ww + (side ? Ww - 1 : 0);
        float vt = __half2float(Tc[a]);
        float vp = __half2float(Pc[a]);
        float* e0 = sCt + row * RSTR + (side ? 164 : 0);
        float* e1 = sCp + row * RSTR + (side ? 164 : 0);
        e0[0] = vt; e0[1] = vt; e0[2] = vt; e0[3] = vt;
        e1[0] = vp; e1[1] = vp; e1[2] = vp; e1[3] = vp;
    }
    __syncthreads();

#pragma unroll
    for (int q = 0; q < 3; ++q) {
        __half* __restrict__ dst = g_h[q == 0 ? 0 : (q == 1 ? 1 : 4)];
        // ---- W: products + running strip sums ----
        for (int u = tid; u < CHH * 40; u += NT1) {
            int row = u / 40, s = u % 40;
            const float* ra = (q == 2 ? sCp : sCt) + row * RSTR + 4 * s;
            const float* rb = (q == 1 ? sCt : sCp) + row * RSTR + 4 * s;
            float4 a0 = *(const float4*)ra, a1 = *(const float4*)(ra + 4), a2 = *(const float4*)(ra + 8);
            float4 b0 = *(const float4*)rb, b1 = *(const float4*)(rb + 4), b2 = *(const float4*)(rb + 8);
            float v0 = a0.x * b0.x, v1 = a0.y * b0.y, v2 = a0.z * b0.z, v3 = a0.w * b0.w;
            float v4 = a1.x * b1.x, v5 = a1.y * b1.y, v6 = a1.z * b1.z, v7 = a1.w * b1.w;
            float v8 = a2.x * b2.x, v9 = a2.y * b2.y, v10 = a2.z * b2.z, v11 = a2.w * b2.w;
            float s0 = v0 + v1 + v2 + v3 + v4 + v5 + v6 + v7 + v8;
            float s1 = s0 - v0 + v9;
            float s2 = s1 - v1 + v10;
            float s3 = s2 - v2 + v11;
            *(float4*)(sW + row * 160 + 4 * s) = make_float4(s0, s1, s2, s3);
        }
        __syncthreads();
        // ---- H: running sums + fp16 store ----
        {
            const int r0 = ty * 12;
            const float* c = sW + tx;
            float s = c[(r0 + 0) * 160] + c[(r0 + 1) * 160] + c[(r0 + 2) * 160]
                    + c[(r0 + 3) * 160] + c[(r0 + 4) * 160] + c[(r0 + 5) * 160]
                    + c[(r0 + 6) * 160] + c[(r0 + 7) * 160] + c[(r0 + 8) * 160];
            __half* o = dst + pl + (long)(h0c + r0) * Ww + tx;
            o[0] = __float2half_rn(s);
#pragma unroll
            for (int k = 1; k < 12; ++k) {
                s += c[(r0 + k + 8) * 160] - c[(r0 + k - 1) * 160];
                o[(long)k * Ww] = __float2half_rn(s);
            }
        }
        __syncthreads();
    }
}

// ===========================================================================
// K4: D-axis running box sums of SA,SB,SC (fp16) + cc + mean reduction.
// ===========================================================================
__global__ __launch_bounds__(256, 6)
void k_d3cc(float* __restrict__ out) {
    const int b = blockIdx.z;
    const int hw = blockIdx.x * 256 + threadIdx.x;
    const int d0 = blockIdx.y * CD2;
    const __half* __restrict__ A = g_h[0];
    const __half* __restrict__ B = g_h[1];
    const __half* __restrict__ C = g_h[4];
    const long base = (long)b * DHW + hw;

    float sa = 0.f, sb = 0.f, sc = 0.f;
#pragma unroll
    for (int j = -4; j <= 4; ++j) {
        long a = base + (long)clampi(d0 + j, 0, Dd - 1) * HW;
        sa += __half2float(A[a]);
        sb += __half2float(B[a]);
        sc += __half2float(C[a]);
    }
    float acc = fminf(fmaxf(__fdividef(sa * sa + EPSL, sb * sc + EPSL), 0.f), 1.f);
#pragma unroll 4
    for (int d = d0 + 1; d < d0 + CD2; ++d) {
        long ap = base + (long)min(d + 4, Dd - 1) * HW;
        long am = base + (long)max(d - 5, 0) * HW;
        sa += __half2float(A[ap]) - __half2float(A[am]);
        sb += __half2float(B[ap]) - __half2float(B[am]);
        sc += __half2float(C[ap]) - __half2float(C[am]);
        acc += fminf(fmaxf(__fdividef(sa * sa + EPSL, sb * sc + EPSL), 0.f), 1.f);
    }

    __shared__ float red[256];
    red[threadIdx.x] = acc;
    __syncthreads();
#pragma unroll
    for (int s = 128; s > 0; s >>= 1) {
        if (threadIdx.x < s) red[threadIdx.x] += red[threadIdx.x + s];
        __syncthreads();
    }
    if (threadIdx.x == 0) atomicAdd(out, -red[0] * (1.0f / (float)NTOT));
}

// ===========================================================================
extern "C" void kernel_launch(void* const* d_in, const int* in_sizes, int n_in,
                              void* d_out, int out_size) {
    const float* t = (const float*)d_in[0];  // y_true
    const float* p = (const float*)d_in[1];  // y_pred
    float* out = (float*)d_out;

    static const int SM1 = (CHH * RSTR + CHH * 160) * 4;       // 73472 B
    static const int SM3 = (2 * CHH * RSTR + CHH * 160) * 4;   // 111104 B
    cudaFuncSetAttribute(k_wh2,    cudaFuncAttributeMaxDynamicSharedMemorySize, SM1);
    cudaFuncSetAttribute(k_prodwh, cudaFuncAttributeMaxDynamicSharedMemorySize, SM3);

    const dim3 bwh(160, 4);
    const dim3 gwh(Hh / CHO, Dd, Bsz);                  // (4, 160, 2)
    const dim3 gcol(HW / 256, Dd / CD2, Bsz);           // (120, 2, 2)

    k_wh2<<<gwh, bwh, SM1>>>(t, p, out);
    k_dcenter<<<gcol, 256>>>(t, p);
    k_prodwh<<<gwh, bwh, SM3>>>();
    k_d3cc<<<gcol, 256>>>(out);
}

// round 6
// speedup vs baseline: 2.5037x; 1.3367x over previous
#include <cuda_runtime.h>
#include <cuda_fp16.h>

// Geometry: [B=2, C=1, D=160, H=192, W=160] fp32.
#define Bsz 2
#define Dd  160
#define Hh  192
#define Ww  160
#define HW  (Hh * Ww)
#define DHW (Dd * HW)
#define NTOT (Bsz * DHW)
#define INV_V (1.0f / 729.0f)
#define EPSL 1e-6f

// WH tiling: full W rows, CHO output H-rows (+8 halo), padded row stride.
#define CHO 48
#define CHH 56          // CHO + 8
#define RSTR 168        // 4 + 160 + 4
#define NT1 640         // blockDim (160, 4)

#define CD2 20          // D-chunk for column kernels (960 blocks)

// Half intermediates: [0]=St/SA [1]=Sp/SB [2]=tc [3]=pc [4]=SC  (98.3 MB)
__device__ __half g_h[5][NTOT];

__device__ __forceinline__ int clampi(int v, int lo, int hi) {
    return min(max(v, lo), hi);
}

// ===========================================================================
// K1: per-plane W+H 9x9 box sums of t and p -> g_h[0], g_h[1] (fp16).
// Also zeroes the output scalar. smem: sIn[56][168] + sW[56][160] = 73472 B.
// ===========================================================================
__global__ __launch_bounds__(NT1, 3)
void k_wh2(const float* __restrict__ t, const float* __restrict__ p,
           float* __restrict__ out) {
    extern __shared__ float sm[];
    float* sIn = sm;
    float* sW  = sm + CHH * RSTR;

    const int tx = threadIdx.x, ty = threadIdx.y;
    const int tid = ty * 160 + tx;
    if (blockIdx.x == 0 && blockIdx.y == 0 && blockIdx.z == 0 && tid == 0)
        *out = 0.f;
    const int h0c = blockIdx.x * CHO;
    const long pl = (long)blockIdx.z * DHW + (long)blockIdx.y * HW;

    for (int f = 0; f < 2; ++f) {
        const float* __restrict__ src = f ? p : t;
        __half* __restrict__ dst = g_h[f];
        for (int u = tid; u < CHH * 40; u += NT1) {
            int row = u / 40, c4 = u % 40;
            int gh = clampi(h0c - 4 + row, 0, Hh - 1);
            float4 v = *(const float4*)(src + pl + (long)gh * Ww + c4 * 4);
            *(float4*)(sIn + row * RSTR + 4 + c4 * 4) = v;
        }
        if (tid < CHH * 2) {
            int row = tid >> 1, side = tid & 1;
            int gh = clampi(h0c - 4 + row, 0, Hh - 1);
            float v = src[pl + (long)gh * Ww + (side ? Ww - 1 : 0)];
            float* e = sIn + row * RSTR + (side ? 164 : 0);
            e[0] = v; e[1] = v; e[2] = v; e[3] = v;
        }
        __syncthreads();
        for (int u = tid; u < CHH * 40; u += NT1) {
            int row = u / 40, s = u % 40;
            const float* rp = sIn + row * RSTR + 4 * s;
            float4 x0 = *(const float4*)rp;
            float4 x1 = *(const float4*)(rp + 4);
            float4 x2 = *(const float4*)(rp + 8);
            float s0 = x0.x + x0.y + x0.z + x0.w + x1.x + x1.y + x1.z + x1.w + x2.x;
            float s1 = s0 - x0.x + x2.y;
            float s2 = s1 - x0.y + x2.z;
            float s3 = s2 - x0.z + x2.w;
            *(float4*)(sW + row * 160 + 4 * s) = make_float4(s0, s1, s2, s3);
        }
        __syncthreads();
        {
            const int r0 = ty * 12;
            const float* c = sW + tx;
            float s = c[(r0 + 0) * 160] + c[(r0 + 1) * 160] + c[(r0 + 2) * 160]
                    + c[(r0 + 3) * 160] + c[(r0 + 4) * 160] + c[(r0 + 5) * 160]
                    + c[(r0 + 6) * 160] + c[(r0 + 7) * 160] + c[(r0 + 8) * 160];
            __half* o = dst + pl + (long)(h0c + r0) * Ww + tx;
            o[0] = __float2half_rn(s);
#pragma unroll
            for (int k = 1; k < 12; ++k) {
                s += c[(r0 + k + 8) * 160] - c[(r0 + k - 1) * 160];
                o[(long)k * Ww] = __float2half_rn(s);
            }
        }
        __syncthreads();
    }
}

// ===========================================================================
// K2: D-axis running box sum of St,Sp -> means; fused centering.
// Thread = 2 adjacent (b,hw) columns (half2/float2 I/O), sweeps CD2 planes.
// grid (HW/512, D/CD2, B) = (60, 8, 2).
// ===========================================================================
__global__ __launch_bounds__(256, 6)
void k_dcenter(const float* __restrict__ t, const float* __restrict__ p) {
    const int b = blockIdx.z;
    const int hw = (blockIdx.x * 256 + threadIdx.x) * 2;
    const int d0 = blockIdx.y * CD2;
    const __half* __restrict__ St = g_h[0];
    const __half* __restrict__ Sp = g_h[1];
    __half* __restrict__ Tc = g_h[2];
    __half* __restrict__ Pc = g_h[3];
    const long base = (long)b * DHW + hw;

    float2 sa = make_float2(0.f, 0.f), sb = sa;
#pragma unroll
    for (int j = -4; j <= 4; ++j) {
        long a = base + (long)clampi(d0 + j, 0, Dd - 1) * HW;
        float2 va = __half22float2(*(const __half2*)(St + a));
        float2 vb = __half22float2(*(const __half2*)(Sp + a));
        sa.x += va.x; sa.y += va.y;
        sb.x += vb.x; sb.y += vb.y;
    }
    {
        long a = base + (long)d0 * HW;
        float2 vt = *(const float2*)(t + a);
        float2 vp = *(const float2*)(p + a);
        *(__half2*)(Tc + a) = __floats2half2_rn(vt.x - sa.x * INV_V, vt.y - sa.y * INV_V);
        *(__half2*)(Pc + a) = __floats2half2_rn(vp.x - sb.x * INV_V, vp.y - sb.y * INV_V);
    }
#pragma unroll 4
    for (int d = d0 + 1; d < d0 + CD2; ++d) {
        long ap = base + (long)min(d + 4, Dd - 1) * HW;
        long am = base + (long)max(d - 5, 0) * HW;
        float2 pa = __half22float2(*(const __half2*)(St + ap));
        float2 ma = __half22float2(*(const __half2*)(St + am));
        float2 pb = __half22float2(*(const __half2*)(Sp + ap));
        float2 mb = __half22float2(*(const __half2*)(Sp + am));
        sa.x += pa.x - ma.x; sa.y += pa.y - ma.y;
        sb.x += pb.x - mb.x; sb.y += pb.y - mb.y;
        long a = base + (long)d * HW;
        float2 vt = *(const float2*)(t + a);
        float2 vp = *(const float2*)(p + a);
        *(__half2*)(Tc + a) = __floats2half2_rn(vt.x - sa.x * INV_V, vt.y - sa.y * INV_V);
        *(__half2*)(Pc + a) = __floats2half2_rn(vp.x - sb.x * INV_V, vp.y - sb.y * INV_V);
    }
}

// ===========================================================================
// K3: per-plane W+H box sums of (tc*pc, tc^2, pc^2) from fp16 tc,pc.
// smem: sCt/sCp half[56][168] (37632 B) + sW fp32[56][160] (35840 B) = 73472 B.
// ===========================================================================
__global__ __launch_bounds__(NT1, 3)
void k_prodwh() {
    extern __shared__ float sm[];
    __half* sCt = (__half*)sm;
    __half* sCp = sCt + CHH * RSTR;
    float*  sW  = sm + (2 * CHH * RSTR) / 2;   // after 2*CHH*RSTR halves

    const int tx = threadIdx.x, ty = threadIdx.y;
    const int tid = ty * 160 + tx;
    const int h0c = blockIdx.x * CHO;
    const long pl = (long)blockIdx.z * DHW + (long)blockIdx.y * HW;
    const __half* __restrict__ Tc = g_h[2];
    const __half* __restrict__ Pc = g_h[3];

    // ---- load centered fields (half -> half smem, raw 8B copies) ----
    for (int u = tid; u < CHH * 40; u += NT1) {
        int row = u / 40, c4 = u % 40;
        int gh = clampi(h0c - 4 + row, 0, Hh - 1);
        const long a = pl + (long)gh * Ww + c4 * 4;
        *(uint2*)(sCt + row * RSTR + 4 + c4 * 4) = *(const uint2*)(Tc + a);
        *(uint2*)(sCp + row * RSTR + 4 + c4 * 4) = *(const uint2*)(Pc + a);
    }
    if (tid < CHH * 2) {
        int row = tid >> 1, side = tid & 1;
        int gh = clampi(h0c - 4 + row, 0, Hh - 1);
        const long a = pl + (long)gh * Ww + (side ? Ww - 1 : 0);
        __half vt = Tc[a], vp = Pc[a];
        __half* e0 = sCt + row * RSTR + (side ? 164 : 0);
        __half* e1 = sCp + row * RSTR + (side ? 164 : 0);
        e0[0] = vt; e0[1] = vt; e0[2] = vt; e0[3] = vt;
        e1[0] = vp; e1[1] = vp; e1[2] = vp; e1[3] = vp;
    }
    __syncthreads();

#pragma unroll
    for (int q = 0; q < 3; ++q) {
        __half* __restrict__ dst = g_h[q == 0 ? 0 : (q == 1 ? 1 : 4)];
        for (int u = tid; u < CHH * 40; u += NT1) {
            int row = u / 40, s = u % 40;
            const __half* ra = (q == 2 ? sCp : sCt) + row * RSTR + 4 * s;
            const __half* rb = (q == 1 ? sCt : sCp) + row * RSTR + 4 * s;
            float2 a01 = __half22float2(*(const __half2*)(ra));
            float2 a23 = __half22float2(*(const __half2*)(ra + 2));
            float2 a45 = __half22float2(*(const __half2*)(ra + 4));
            float2 a67 = __half22float2(*(const __half2*)(ra + 6));
            float2 a89 = __half22float2(*(const __half2*)(ra + 8));
            float2 aAB = __half22float2(*(const __half2*)(ra + 10));
            float2 b01 = __half22float2(*(const __half2*)(rb));
            float2 b23 = __half22float2(*(const __half2*)(rb + 2));
            float2 b45 = __half22float2(*(const __half2*)(rb + 4));
            float2 b67 = __half22float2(*(const __half2*)(rb + 6));
            float2 b89 = __half22float2(*(const __half2*)(rb + 8));
            float2 bAB = __half22float2(*(const __half2*)(rb + 10));
            float v0 = a01.x * b01.x, v1 = a01.y * b01.y;
            float v2 = a23.x * b23.x, v3 = a23.y * b23.y;
            float v4 = a45.x * b45.x, v5 = a45.y * b45.y;
            float v6 = a67.x * b67.x, v7 = a67.y * b67.y;
            float v8 = a89.x * b89.x, v9 = a89.y * b89.y;
            float v10 = aAB.x * bAB.x, v11 = aAB.y * bAB.y;
            float s0 = v0 + v1 + v2 + v3 + v4 + v5 + v6 + v7 + v8;
            float s1 = s0 - v0 + v9;
            float s2 = s1 - v1 + v10;
            float s3 = s2 - v2 + v11;
            *(float4*)(sW + row * 160 + 4 * s) = make_float4(s0, s1, s2, s3);
        }
        __syncthreads();
        {
            const int r0 = ty * 12;
            const float* c = sW + tx;
            float s = c[(r0 + 0) * 160] + c[(r0 + 1) * 160] + c[(r0 + 2) * 160]
                    + c[(r0 + 3) * 160] + c[(r0 + 4) * 160] + c[(r0 + 5) * 160]
                    + c[(r0 + 6) * 160] + c[(r0 + 7) * 160] + c[(r0 + 8) * 160];
            __half* o = dst + pl + (long)(h0c + r0) * Ww + tx;
            o[0] = __float2half_rn(s);
#pragma unroll
            for (int k = 1; k < 12; ++k) {
                s += c[(r0 + k + 8) * 160] - c[(r0 + k - 1) * 160];
                o[(long)k * Ww] = __float2half_rn(s);
            }
        }
        __syncthreads();
    }
}

// ===========================================================================
// K4: D-axis running box sums of SA,SB,SC (fp16, half2 x2 columns) + cc +
// mean reduction.
// ===========================================================================
__global__ __launch_bounds__(256, 6)
void k_d3cc(float* __restrict__ out) {
    const int b = blockIdx.z;
    const int hw = (blockIdx.x * 256 + threadIdx.x) * 2;
    const int d0 = blockIdx.y * CD2;
    const __half* __restrict__ A = g_h[0];
    const __half* __restrict__ B = g_h[1];
    const __half* __restrict__ C = g_h[4];
    const long base = (long)b * DHW + hw;

    float2 sa = make_float2(0.f, 0.f), sb = sa, sc = sa;
#pragma unroll
    for (int j = -4; j <= 4; ++j) {
        long a = base + (long)clampi(d0 + j, 0, Dd - 1) * HW;
        float2 va = __half22float2(*(const __half2*)(A + a));
        float2 vb = __half22float2(*(const __half2*)(B + a));
        float2 vc = __half22float2(*(const __half2*)(C + a));
        sa.x += va.x; sa.y += va.y;
        sb.x += vb.x; sb.y += vb.y;
        sc.x += vc.x; sc.y += vc.y;
    }
    float acc = fminf(fmaxf(__fdividef(sa.x * sa.x + EPSL, sb.x * sc.x + EPSL), 0.f), 1.f)
              + fminf(fmaxf(__fdividef(sa.y * sa.y + EPSL, sb.y * sc.y + EPSL), 0.f), 1.f);
#pragma unroll 4
    for (int d = d0 + 1; d < d0 + CD2; ++d) {
        long ap = base + (long)min(d + 4, Dd - 1) * HW;
        long am = base + (long)max(d - 5, 0) * HW;
        float2 pa = __half22float2(*(const __half2*)(A + ap));
        float2 ma = __half22float2(*(const __half2*)(A + am));
        float2 pb = __half22float2(*(const __half2*)(B + ap));
        float2 mb = __half22float2(*(const __half2*)(B + am));
        float2 pc = __half22float2(*(const __half2*)(C + ap));
        float2 mc = __half22float2(*(const __half2*)(C + am));
        sa.x += pa.x - ma.x; sa.y += pa.y - ma.y;
        sb.x += pb.x - mb.x; sb.y += pb.y - mb.y;
        sc.x += pc.x - mc.x; sc.y += pc.y - mc.y;
        acc += fminf(fmaxf(__fdividef(sa.x * sa.x + EPSL, sb.x * sc.x + EPSL), 0.f), 1.f)
             + fminf(fmaxf(__fdividef(sa.y * sa.y + EPSL, sb.y * sc.y + EPSL), 0.f), 1.f);
    }

    __shared__ float red[256];
    red[threadIdx.x] = acc;
    __syncthreads();
#pragma unroll
    for (int s = 128; s > 0; s >>= 1) {
        if (threadIdx.x < s) red[threadIdx.x] += red[threadIdx.x + s];
        __syncthreads();
    }
    if (threadIdx.x == 0) atomicAdd(out, -red[0] * (1.0f / (float)NTOT));
}

// ===========================================================================
extern "C" void kernel_launch(void* const* d_in, const int* in_sizes, int n_in,
                              void* d_out, int out_size) {
    const float* t = (const float*)d_in[0];  // y_true
    const float* p = (const float*)d_in[1];  // y_pred
    float* out = (float*)d_out;

    static const int SMWH = (CHH * RSTR + CHH * 160) * 4;   // 73472 B (both)
    cudaFuncSetAttribute(k_wh2,    cudaFuncAttributeMaxDynamicSharedMemorySize, SMWH);
    cudaFuncSetAttribute(k_prodwh, cudaFuncAttributeMaxDynamicSharedMemorySize, SMWH);

    const dim3 bwh(160, 4);
    const dim3 gwh(Hh / CHO, Dd, Bsz);               // (4, 160, 2)
    const dim3 gcol(HW / 512, Dd / CD2, Bsz);        // (60, 8, 2) = 960 blocks

    k_wh2<<<gwh, bwh, SMWH>>>(t, p, out);
    k_dcenter<<<gcol, 256>>>(t, p);
    k_prodwh<<<gwh, bwh, SMWH>>>();
    k_d3cc<<<gcol, 256>>>(out);
}

// round 7
// speedup vs baseline: 2.8137x; 1.1238x over previous
#include <cuda_runtime.h>
#include <cuda_fp16.h>

// Geometry: [B=2, C=1, D=160, H=192, W=160] fp32.
#define Bsz 2
#define Dd  160
#define Hh  192
#define Ww  160
#define HW  (Hh * Ww)
#define DHW (Dd * HW)
#define NTOT (Bsz * DHW)
#define INV_V (1.0f / 729.0f)
#define EPSL 1e-6f

// WH tiling: full W rows, CHO output H-rows (+8 halo), padded row stride.
#define CHO 48
#define CHH 56          // CHO + 8
#define RSTR 168        // 4 + 160 + 4
#define NT1 640         // blockDim (160, 4)

#define CD2 20          // D-chunk for column kernels

// Half intermediates: [0]=St/SA [1]=Sp/SB [2]=tc [3]=pc [4]=SC  (98.3 MB)
__device__ __half g_h[5][NTOT];

__device__ __forceinline__ int clampi(int v, int lo, int hi) {
    return min(max(v, lo), hi);
}

__device__ __forceinline__ float4 ld_half4(const __half* p) {
    uint2 u = *(const uint2*)p;
    __half2 lo = *reinterpret_cast<__half2*>(&u.x);
    __half2 hi = *reinterpret_cast<__half2*>(&u.y);
    float2 a = __half22float2(lo), b = __half22float2(hi);
    return make_float4(a.x, a.y, b.x, b.y);
}

__device__ __forceinline__ void st_half4(__half* p, float4 v) {
    __half2 lo = __floats2half2_rn(v.x, v.y);
    __half2 hi = __floats2half2_rn(v.z, v.w);
    uint2 u;
    u.x = *reinterpret_cast<unsigned*>(&lo);
    u.y = *reinterpret_cast<unsigned*>(&hi);
    *(uint2*)p = u;
}

// ===========================================================================
// K1: per-plane W+H 9x9 box sums of t and p -> g_h[0], g_h[1] (fp16).
// Also zeroes the output scalar. smem: sIn[56][168] + sW[56][160] = 73472 B.
// ===========================================================================
__global__ __launch_bounds__(NT1, 3)
void k_wh2(const float* __restrict__ t, const float* __restrict__ p,
           float* __restrict__ out) {
    extern __shared__ float sm[];
    float* sIn = sm;
    float* sW  = sm + CHH * RSTR;

    const int tx = threadIdx.x, ty = threadIdx.y;
    const int tid = ty * 160 + tx;
    if (blockIdx.x == 0 && blockIdx.y == 0 && blockIdx.z == 0 && tid == 0)
        *out = 0.f;
    const int h0c = blockIdx.x * CHO;
    const long pl = (long)blockIdx.z * DHW + (long)blockIdx.y * HW;

    for (int f = 0; f < 2; ++f) {
        const float* __restrict__ src = f ? p : t;
        __half* __restrict__ dst = g_h[f];
        for (int u = tid; u < CHH * 40; u += NT1) {
            int row = u / 40, c4 = u % 40;
            int gh = clampi(h0c - 4 + row, 0, Hh - 1);
            float4 v = *(const float4*)(src + pl + (long)gh * Ww + c4 * 4);
            *(float4*)(sIn + row * RSTR + 4 + c4 * 4) = v;
        }
        if (tid < CHH * 2) {
            int row = tid >> 1, side = tid & 1;
            int gh = clampi(h0c - 4 + row, 0, Hh - 1);
            float v = src[pl + (long)gh * Ww + (side ? Ww - 1 : 0)];
            float* e = sIn + row * RSTR + (side ? 164 : 0);
            e[0] = v; e[1] = v; e[2] = v; e[3] = v;
        }
        __syncthreads();
        for (int u = tid; u < CHH * 40; u += NT1) {
            int row = u / 40, s = u % 40;
            const float* rp = sIn + row * RSTR + 4 * s;
            float4 x0 = *(const float4*)rp;
            float4 x1 = *(const float4*)(rp + 4);
            float4 x2 = *(const float4*)(rp + 8);
            float s0 = x0.x + x0.y + x0.z + x0.w + x1.x + x1.y + x1.z + x1.w + x2.x;
            float s1 = s0 - x0.x + x2.y;
            float s2 = s1 - x0.y + x2.z;
            float s3 = s2 - x0.z + x2.w;
            *(float4*)(sW + row * 160 + 4 * s) = make_float4(s0, s1, s2, s3);
        }
        __syncthreads();
        {
            const int r0 = ty * 12;
            const float* c = sW + tx;
            float s = c[(r0 + 0) * 160] + c[(r0 + 1) * 160] + c[(r0 + 2) * 160]
                    + c[(r0 + 3) * 160] + c[(r0 + 4) * 160] + c[(r0 + 5) * 160]
                    + c[(r0 + 6) * 160] + c[(r0 + 7) * 160] + c[(r0 + 8) * 160];
            __half* o = dst + pl + (long)(h0c + r0) * Ww + tx;
            o[0] = __float2half_rn(s);
#pragma unroll
            for (int k = 1; k < 12; ++k) {
                s += c[(r0 + k + 8) * 160] - c[(r0 + k - 1) * 160];
                o[(long)k * Ww] = __float2half_rn(s);
            }
        }
        __syncthreads();
    }
}

// ===========================================================================
// K2: D-axis running box sum of St,Sp -> means; fused centering.
// Thread = 4 adjacent (b,hw) columns (uint2 half I/O, float4 fp32 reads).
// grid (HW/512, D/CD2, B) = (60, 8, 2) = 960 blocks of 128.
// ===========================================================================
__global__ __launch_bounds__(128, 8)
void k_dcenter(const float* __restrict__ t, const float* __restrict__ p) {
    const int b = blockIdx.z;
    const int hw = (blockIdx.x * 128 + threadIdx.x) * 4;
    const int d0 = blockIdx.y * CD2;
    const __half* __restrict__ St = g_h[0];
    const __half* __restrict__ Sp = g_h[1];
    __half* __restrict__ Tc = g_h[2];
    __half* __restrict__ Pc = g_h[3];
    const long base = (long)b * DHW + hw;

    float4 sa = make_float4(0.f, 0.f, 0.f, 0.f), sb = sa;
#pragma unroll
    for (int j = -4; j <= 4; ++j) {
        long a = base + (long)clampi(d0 + j, 0, Dd - 1) * HW;
        float4 va = ld_half4(St + a);
        float4 vb = ld_half4(Sp + a);
        sa.x += va.x; sa.y += va.y; sa.z += va.z; sa.w += va.w;
        sb.x += vb.x; sb.y += vb.y; sb.z += vb.z; sb.w += vb.w;
    }
    {
        long a = base + (long)d0 * HW;
        float4 vt = *(const float4*)(t + a);
        float4 vp = *(const float4*)(p + a);
        st_half4(Tc + a, make_float4(vt.x - sa.x * INV_V, vt.y - sa.y * INV_V,
                                     vt.z - sa.z * INV_V, vt.w - sa.w * INV_V));
        st_half4(Pc + a, make_float4(vp.x - sb.x * INV_V, vp.y - sb.y * INV_V,
                                     vp.z - sb.z * INV_V, vp.w - sb.w * INV_V));
    }
#pragma unroll 4
    for (int d = d0 + 1; d < d0 + CD2; ++d) {
        long ap = base + (long)min(d + 4, Dd - 1) * HW;
        long am = base + (long)max(d - 5, 0) * HW;
        float4 pa = ld_half4(St + ap), ma = ld_half4(St + am);
        float4 pb = ld_half4(Sp + ap), mb = ld_half4(Sp + am);
        sa.x += pa.x - ma.x; sa.y += pa.y - ma.y;
        sa.z += pa.z - ma.z; sa.w += pa.w - ma.w;
        sb.x += pb.x - mb.x; sb.y += pb.y - mb.y;
        sb.z += pb.z - mb.z; sb.w += pb.w - mb.w;
        long a = base + (long)d * HW;
        float4 vt = *(const float4*)(t + a);
        float4 vp = *(const float4*)(p + a);
        st_half4(Tc + a, make_float4(vt.x - sa.x * INV_V, vt.y - sa.y * INV_V,
                                     vt.z - sa.z * INV_V, vt.w - sa.w * INV_V));
        st_half4(Pc + a, make_float4(vp.x - sb.x * INV_V, vp.y - sb.y * INV_V,
                                     vp.z - sb.z * INV_V, vp.w - sb.w * INV_V));
    }
}

// ===========================================================================
// K3: per-plane W+H box sums of (tc*pc, tc^2, pc^2) from fp16 tc,pc.
// smem: sCt/sCp half[56][168] + sW fp32[56][160] = 73472 B.
// ===========================================================================
__global__ __launch_bounds__(NT1, 3)
void k_prodwh() {
    extern __shared__ float sm[];
    __half* sCt = (__half*)sm;
    __half* sCp = sCt + CHH * RSTR;
    float*  sW  = sm + (2 * CHH * RSTR) / 2;

    const int tx = threadIdx.x, ty = threadIdx.y;
    const int tid = ty * 160 + tx;
    const int h0c = blockIdx.x * CHO;
    const long pl = (long)blockIdx.z * DHW + (long)blockIdx.y * HW;
    const __half* __restrict__ Tc = g_h[2];
    const __half* __restrict__ Pc = g_h[3];

    for (int u = tid; u < CHH * 40; u += NT1) {
        int row = u / 40, c4 = u % 40;
        int gh = clampi(h0c - 4 + row, 0, Hh - 1);
        const long a = pl + (long)gh * Ww + c4 * 4;
        *(uint2*)(sCt + row * RSTR + 4 + c4 * 4) = *(const uint2*)(Tc + a);
        *(uint2*)(sCp + row * RSTR + 4 + c4 * 4) = *(const uint2*)(Pc + a);
    }
    if (tid < CHH * 2) {
        int row = tid >> 1, side = tid & 1;
        int gh = clampi(h0c - 4 + row, 0, Hh - 1);
        const long a = pl + (long)gh * Ww + (side ? Ww - 1 : 0);
        __half vt = Tc[a], vp = Pc[a];
        __half* e0 = sCt + row * RSTR + (side ? 164 : 0);
        __half* e1 = sCp + row * RSTR + (side ? 164 : 0);
        e0[0] = vt; e0[1] = vt; e0[2] = vt; e0[3] = vt;
        e1[0] = vp; e1[1] = vp; e1[2] = vp; e1[3] = vp;
    }
    __syncthreads();

#pragma unroll
    for (int q = 0; q < 3; ++q) {
        __half* __restrict__ dst = g_h[q == 0 ? 0 : (q == 1 ? 1 : 4)];
        for (int u = tid; u < CHH * 40; u += NT1) {
            int row = u / 40, s = u % 40;
            const __half* ra = (q == 2 ? sCp : sCt) + row * RSTR + 4 * s;
            const __half* rb = (q == 1 ? sCt : sCp) + row * RSTR + 4 * s;
            float2 a01 = __half22float2(*(const __half2*)(ra));
            float2 a23 = __half22float2(*(const __half2*)(ra + 2));
            float2 a45 = __half22float2(*(const __half2*)(ra + 4));
            float2 a67 = __half22float2(*(const __half2*)(ra + 6));
            float2 a89 = __half22float2(*(const __half2*)(ra + 8));
            float2 aAB = __half22float2(*(const __half2*)(ra + 10));
            float2 b01 = __half22float2(*(const __half2*)(rb));
            float2 b23 = __half22float2(*(const __half2*)(rb + 2));
            float2 b45 = __half22float2(*(const __half2*)(rb + 4));
            float2 b67 = __half22float2(*(const __half2*)(rb + 6));
            float2 b89 = __half22float2(*(const __half2*)(rb + 8));
            float2 bAB = __half22float2(*(const __half2*)(rb + 10));
            float v0 = a01.x * b01.x, v1 = a01.y * b01.y;
            float v2 = a23.x * b23.x, v3 = a23.y * b23.y;
            float v4 = a45.x * b45.x, v5 = a45.y * b45.y;
            float v6 = a67.x * b67.x, v7 = a67.y * b67.y;
            float v8 = a89.x * b89.x, v9 = a89.y * b89.y;
            float v10 = aAB.x * bAB.x, v11 = aAB.y * bAB.y;
            float s0 = v0 + v1 + v2 + v3 + v4 + v5 + v6 + v7 + v8;
            float s1 = s0 - v0 + v9;
            float s2 = s1 - v1 + v10;
            float s3 = s2 - v2 + v11;
            *(float4*)(sW + row * 160 + 4 * s) = make_float4(s0, s1, s2, s3);
        }
        __syncthreads();
        {
            const int r0 = ty * 12;
            const float* c = sW + tx;
            float s = c[(r0 + 0) * 160] + c[(r0 + 1) * 160] + c[(r0 + 2) * 160]
                    + c[(r0 + 3) * 160] + c[(r0 + 4) * 160] + c[(r0 + 5) * 160]
                    + c[(r0 + 6) * 160] + c[(r0 + 7) * 160] + c[(r0 + 8) * 160];
            __half* o = dst + pl + (long)(h0c + r0) * Ww + tx;
            o[0] = __float2half_rn(s);
#pragma unroll
            for (int k = 1; k < 12; ++k) {
                s += c[(r0 + k + 8) * 160] - c[(r0 + k - 1) * 160];
                o[(long)k * Ww] = __float2half_rn(s);
            }
        }
        __syncthreads();
    }
}

// ===========================================================================
// K4: D-axis running box sums of SA,SB,SC (fp16, 4 columns/thread) + cc +
// mean reduction. grid (60, 8, 2) = 960 blocks of 128.
// ===========================================================================
__global__ __launch_bounds__(128, 8)
void k_d3cc(float* __restrict__ out) {
    const int b = blockIdx.z;
    const int hw = (blockIdx.x * 128 + threadIdx.x) * 4;
    const int d0 = blockIdx.y * CD2;
    const __half* __restrict__ A = g_h[0];
    const __half* __restrict__ B = g_h[1];
    const __half* __restrict__ C = g_h[4];
    const long base = (long)b * DHW + hw;

    float4 sa = make_float4(0.f, 0.f, 0.f, 0.f), sb = sa, sc = sa;
#pragma unroll
    for (int j = -4; j <= 4; ++j) {
        long a = base + (long)clampi(d0 + j, 0, Dd - 1) * HW;
        float4 va = ld_half4(A + a);
        float4 vb = ld_half4(B + a);
        float4 vc = ld_half4(C + a);
        sa.x += va.x; sa.y += va.y; sa.z += va.z; sa.w += va.w;
        sb.x += vb.x; sb.y += vb.y; sb.z += vb.z; sb.w += vb.w;
        sc.x += vc.x; sc.y += vc.y; sc.z += vc.z; sc.w += vc.w;
    }
    float acc =
        fminf(fmaxf(__fdividef(sa.x * sa.x + EPSL, sb.x * sc.x + EPSL), 0.f), 1.f)
      + fminf(fmaxf(__fdividef(sa.y * sa.y + EPSL, sb.y * sc.y + EPSL), 0.f), 1.f)
      + fminf(fmaxf(__fdividef(sa.z * sa.z + EPSL, sb.z * sc.z + EPSL), 0.f), 1.f)
      + fminf(fmaxf(__fdividef(sa.w * sa.w + EPSL, sb.w * sc.w + EPSL), 0.f), 1.f);
#pragma unroll 4
    for (int d = d0 + 1; d < d0 + CD2; ++d) {
        long ap = base + (long)min(d + 4, Dd - 1) * HW;
        long am = base + (long)max(d - 5, 0) * HW;
        float4 pa = ld_half4(A + ap), ma = ld_half4(A + am);
        float4 pb = ld_half4(B + ap), mb = ld_half4(B + am);
        float4 pc = ld_half4(C + ap), mc = ld_half4(C + am);
        sa.x += pa.x - ma.x; sa.y += pa.y - ma.y;
        sa.z += pa.z - ma.z; sa.w += pa.w - ma.w;
        sb.x += pb.x - mb.x; sb.y += pb.y - mb.y;
        sb.z += pb.z - mb.z; sb.w += pb.w - mb.w;
        sc.x += pc.x - mc.x; sc.y += pc.y - mc.y;
        sc.z += pc.z - mc.z; sc.w += pc.w - mc.w;
        acc +=
            fminf(fmaxf(__fdividef(sa.x * sa.x + EPSL, sb.x * sc.x + EPSL), 0.f), 1.f)
          + fminf(fmaxf(__fdividef(sa.y * sa.y + EPSL, sb.y * sc.y + EPSL), 0.f), 1.f)
          + fminf(fmaxf(__fdividef(sa.z * sa.z + EPSL, sb.z * sc.z + EPSL), 0.f), 1.f)
          + fminf(fmaxf(__fdividef(sa.w * sa.w + EPSL, sb.w * sc.w + EPSL), 0.f), 1.f);
    }

    __shared__ float red[128];
    red[threadIdx.x] = acc;
    __syncthreads();
#pragma unroll
    for (int s = 64; s > 0; s >>= 1) {
        if (threadIdx.x < s) red[threadIdx.x] += red[threadIdx.x + s];
        __syncthreads();
    }
    if (threadIdx.x == 0) atomicAdd(out, -red[0] * (1.0f / (float)NTOT));
}

// ===========================================================================
extern "C" void kernel_launch(void* const* d_in, const int* in_sizes, int n_in,
                              void* d_out, int out_size) {
    const float* t = (const float*)d_in[0];  // y_true
    const float* p = (const float*)d_in[1];  // y_pred
    float* out = (float*)d_out;

    static const int SMWH = (CHH * RSTR + CHH * 160) * 4;   // 73472 B (both)
    cudaFuncSetAttribute(k_wh2,    cudaFuncAttributeMaxDynamicSharedMemorySize, SMWH);
    cudaFuncSetAttribute(k_prodwh, cudaFuncAttributeMaxDynamicSharedMemorySize, SMWH);

    const dim3 bwh(160, 4);
    const dim3 gwh(Hh / CHO, Dd, Bsz);               // (4, 160, 2)
    const dim3 gcol(HW / 512, Dd / CD2, Bsz);        // (60, 8, 2) = 960 blocks

    k_wh2<<<gwh, bwh, SMWH>>>(t, p, out);
    k_dcenter<<<gcol, 128>>>(t, p);
    k_prodwh<<<gwh, bwh, SMWH>>>();
    k_d3cc<<<gcol, 128>>>(out);
}